// round 15
// baseline (speedup 1.0000x reference)
#include <cuda_runtime.h>
#include <cuda_fp16.h>
#include <math.h>

// ---------------------------------------------------------------------------
// Spatial_SelfAttention. R15: GEMMs rebuilt with cp.async double-buffered
// k64 slabs (1 barrier/slab vs 2/k16); QKV fused into one launch; weight
// conversions fused. Numerics bit-identical to R14 (same mma order).
// Attention (E-cache two-pass) unchanged.
// ---------------------------------------------------------------------------

#define D_MODEL 1024
#define N_HEAD  16
#define HD      64
#define B_SZ    4
#define SEQ     2048
#define M_ROWS  (B_SZ * SEQ)   // 8192

typedef unsigned short ushort_t;

// Scratch device globals (allocation-free rule)
__device__ ushort_t g_xh[(size_t)M_ROWS * D_MODEL];
__device__ ushort_t g_wq[D_MODEL * D_MODEL], g_wk[D_MODEL * D_MODEL];
__device__ ushort_t g_wv[D_MODEL * D_MODEL], g_wo[D_MODEL * D_MODEL];
__device__ ushort_t g_qh[(size_t)M_ROWS * D_MODEL];
__device__ ushort_t g_kh[(size_t)M_ROWS * D_MODEL];
__device__ ushort_t g_vh[(size_t)M_ROWS * D_MODEL];
__device__ ushort_t g_vth[(size_t)M_ROWS * D_MODEL];
__device__ ushort_t g_oh[(size_t)M_ROWS * D_MODEL];
// E cache: [bh][qt][kt][wid][jp][lane] as uint4 (fragment layout), 536 MB
__device__ uint4    g_e[(size_t)64 * 16 * 16 * 8 * 8 * 32];

// ---- helpers --------------------------------------------------------------
__device__ __forceinline__ ushort_t f2h(float x) {
    __half h = __float2half_rn(x);
    return *reinterpret_cast<ushort_t*>(&h);
}
__device__ __forceinline__ unsigned pack2h(float x, float y) {
    return (unsigned)f2h(x) | ((unsigned)f2h(y) << 16);
}
__device__ __forceinline__ float2 unpack2h(unsigned u) {
    __half2 h = *reinterpret_cast<__half2*>(&u);
    return __half22float2(h);
}
__device__ __forceinline__ void mma16816h(float c[4], const unsigned a[4],
                                          unsigned b0, unsigned b1) {
    asm volatile(
        "mma.sync.aligned.m16n8k16.row.col.f32.f16.f16.f32 "
        "{%0,%1,%2,%3},{%4,%5,%6,%7},{%8,%9},{%0,%1,%2,%3};\n"
        : "+f"(c[0]), "+f"(c[1]), "+f"(c[2]), "+f"(c[3])
        : "r"(a[0]), "r"(a[1]), "r"(a[2]), "r"(a[3]), "r"(b0), "r"(b1));
}
__device__ __forceinline__ void cp16(void* s, const void* g) {
    unsigned sa = (unsigned)__cvta_generic_to_shared(s);
    asm volatile("cp.async.cg.shared.global [%0], [%1], 16;\n" :: "r"(sa), "l"(g));
}
#define CP_COMMIT()  asm volatile("cp.async.commit_group;\n" ::: "memory")
#define CP_WAIT(N)   asm volatile("cp.async.wait_group %0;\n" :: "n"(N) : "memory")

// ---------------------------------------------------------------------------
// convert kernels: fp32 -> packed fp16 pairs
// ---------------------------------------------------------------------------
__global__ void cvt_h(const float* __restrict__ in,
                      unsigned* __restrict__ hi, int n2)
{
    int i = blockIdx.x * blockDim.x + threadIdx.x;
    if (i < n2) {
        float2 v = ((const float2*)in)[i];
        hi[i] = pack2h(v.x, v.y);
    }
}
__global__ void cvt_w4(const float* __restrict__ w0, const float* __restrict__ w1,
                       const float* __restrict__ w2, const float* __restrict__ w3,
                       unsigned* __restrict__ o0, unsigned* __restrict__ o1,
                       unsigned* __restrict__ o2, unsigned* __restrict__ o3,
                       int n2)
{
    int i = blockIdx.x * blockDim.x + threadIdx.x;
    if (i >= n2) return;
    const float* in; unsigned* out;
    switch (blockIdx.y) {
        case 0: in = w0; out = o0; break;
        case 1: in = w1; out = o1; break;
        case 2: in = w2; out = o2; break;
        default: in = w3; out = o3; break;
    }
    float2 v = ((const float2*)in)[i];
    out[i] = pack2h(v.x, v.y);
}

// ---------------------------------------------------------------------------
// V transpose: g_vh [b*2048+l][h*64+d] -> g_vth [(bh*64+d)][l]
// ---------------------------------------------------------------------------
__global__ void vtrans_kernel()
{
    __shared__ ushort_t th[32][33];
    const int bh = blockIdx.z, l0 = blockIdx.x * 32, d0 = blockIdx.y * 32;
    const int b = bh >> 4, h = bh & 15;
    const int tx = threadIdx.x, ty = threadIdx.y;
#pragma unroll
    for (int i = 0; i < 4; i++) {
        int l = l0 + ty + i * 8;
        th[ty + i * 8][tx] = g_vh[(size_t)(b * SEQ + l) * D_MODEL + h * HD + d0 + tx];
    }
    __syncthreads();
#pragma unroll
    for (int i = 0; i < 4; i++) {
        int d = d0 + ty + i * 8;
        g_vth[((size_t)bh * HD + d) * SEQ + l0 + tx] = th[tx][ty + i * 8];
    }
}

// ---------------------------------------------------------------------------
// GEMM core: C[128,128] tile of A[M,K] * W[N,K]^T, fp16 in, fp32 accum.
// cp.async double-buffered k64 slabs; 8 warps, warp tile 32x64.
// smem: [A0][A1][B0][B1], each 128 x 72 shorts (18432 B) -> 73728 B total.
// ---------------------------------------------------------------------------
#define GSTRS 72
#define GBUF  (128 * GSTRS)        // shorts per buffer
#define GEMM_SMEM 73728

__device__ __forceinline__ void gemm_core(
    const ushort_t* __restrict__ Ah, const ushort_t* __restrict__ Bh,
    float* __restrict__ Cf, ushort_t* __restrict__ Ch,
    const float* __restrict__ bias, float oscale,
    int bm, int bn, char* smb)
{
    const int K = D_MODEL, N = D_MODEL;
    ushort_t* sA = (ushort_t*)smb;              // [buf][GBUF]
    ushort_t* sB = (ushort_t*)smb + 2 * GBUF;   // [buf][GBUF]

    const int tid = threadIdx.x;
    const int wid = tid >> 5, lane = tid & 31;
    const int g = lane >> 2, tq = lane & 3;
    const int wm = (wid & 3) * 32, wn = (wid >> 2) * 64;

    float c[2][8][4];
#pragma unroll
    for (int i = 0; i < 2; i++)
#pragma unroll
        for (int j = 0; j < 8; j++)
#pragma unroll
            for (int r = 0; r < 4; r++) c[i][j][r] = 0.f;

    const int row = tid >> 1, db = (tid & 1) * 32;
    const size_t aoff = (size_t)(bm + row) * K + db;
    const size_t boff = (size_t)(bn + row) * K + db;
    const int so = row * GSTRS + db;

    // stage slab s into buffer bf
    auto stage = [&](int s, int bf) {
        const int k0 = s * 64;
#pragma unroll
        for (int i = 0; i < 4; i++) {
            cp16(&sA[bf * GBUF + so + i * 8], Ah + aoff + k0 + i * 8);
            cp16(&sB[bf * GBUF + so + i * 8], Bh + boff + k0 + i * 8);
        }
    };

    stage(0, 0); CP_COMMIT();

    for (int s = 0; s < 16; s++) {
        CP_WAIT(0);
        __syncthreads();
        const int bf = s & 1;
        if (s + 1 < 16) stage(s + 1, (s + 1) & 1);
        CP_COMMIT();
        const ushort_t* cA = sA + bf * GBUF;
        const ushort_t* cB = sB + bf * GBUF;
#pragma unroll
        for (int kk = 0; kk < 4; kk++) {
            const int c0 = kk * 16 + 2 * tq;
            unsigned af[2][4];
#pragma unroll
            for (int i = 0; i < 2; i++) {
                int r0 = wm + i * 16;
                af[i][0] = *(const unsigned*)&cA[(r0 + g)     * GSTRS + c0];
                af[i][1] = *(const unsigned*)&cA[(r0 + g + 8) * GSTRS + c0];
                af[i][2] = *(const unsigned*)&cA[(r0 + g)     * GSTRS + c0 + 8];
                af[i][3] = *(const unsigned*)&cA[(r0 + g + 8) * GSTRS + c0 + 8];
            }
#pragma unroll
            for (int j = 0; j < 8; j++) {
                int n0 = wn + j * 8 + g;
                unsigned b0 = *(const unsigned*)&cB[n0 * GSTRS + c0];
                unsigned b1 = *(const unsigned*)&cB[n0 * GSTRS + c0 + 8];
#pragma unroll
                for (int i = 0; i < 2; i++)
                    mma16816h(c[i][j], af[i], b0, b1);
            }
        }
    }

#pragma unroll
    for (int i = 0; i < 2; i++) {
        int r0 = bm + wm + i * 16 + g;
#pragma unroll
        for (int j = 0; j < 8; j++) {
            int col = bn + wn + j * 8 + 2 * tq;
            float v0 = c[i][j][0] * oscale, v1 = c[i][j][1] * oscale;
            float v2 = c[i][j][2] * oscale, v3 = c[i][j][3] * oscale;
            if (Cf) {
                float bx = bias ? bias[col] : 0.f, by = bias ? bias[col + 1] : 0.f;
                *(float2*)(Cf + (size_t)r0 * N + col)       = make_float2(v0 + bx, v1 + by);
                *(float2*)(Cf + (size_t)(r0 + 8) * N + col) = make_float2(v2 + bx, v3 + by);
            } else {
                *(unsigned*)(Ch + (size_t)r0 * N + col)       = pack2h(v0, v1);
                *(unsigned*)(Ch + (size_t)(r0 + 8) * N + col) = pack2h(v2, v3);
            }
        }
    }
}

// Fused QKV: grid (24, 64); blockIdx.x>>3 selects {Q, K, V}.
__global__ __launch_bounds__(256) void gemm_qkv()
{
    extern __shared__ char smb[];
    const int sel = blockIdx.x >> 3;
    const int bn = (blockIdx.x & 7) * 128;
    const int bm = blockIdx.y * 128;
    const ushort_t* W = (sel == 0) ? g_wq : (sel == 1) ? g_wk : g_wv;
    ushort_t*      Cdst = (sel == 0) ? g_qh : (sel == 1) ? g_kh : g_vh;
    float oscale = (sel == 0) ? 0.125f : 1.0f;   // softmax scale folded into Q
    gemm_core(g_xh, W, nullptr, Cdst, nullptr, oscale, bm, bn, smb);
}

// Output projection: fp32 out + bias.
__global__ __launch_bounds__(256) void gemm_out(float* __restrict__ Cf,
                                                const float* __restrict__ bias)
{
    extern __shared__ char smb[];
    gemm_core(g_oh, g_wo, Cf, nullptr, bias, 1.0f,
              blockIdx.y * 128, blockIdx.x * 128, smb);
}

// ---------------------------------------------------------------------------
// Attention. Pass 1: 1-term scores -> E=exp(s) cached fp16 (fragment layout),
// row sums. Pass 2: load E (same-thread RAW), scale, emit A, AV (1-term).
// smem: two 18432 B buffers (K hi pass 1, V^T double-buffered pass 2).
// ---------------------------------------------------------------------------
#define KSTRS 72
#define VSTRS 136
#define KT    128
#define NKT   (SEQ / KT)
#define KBUF_SH (128 * KSTRS)      // 9216 shorts = 18432 B per buffer
#define ATT_SMEM 36864

__global__ __launch_bounds__(256, 2) void attn2(float* __restrict__ Aout,
                                                int writeA)
{
    extern __shared__ char smb[];
    ushort_t* sK = (ushort_t*)smb;                  // 2 buffers (K, then V^T)

    const int tid = threadIdx.x;
    const int wid = tid >> 5, lane = tid & 31;
    const int g = lane >> 2, tq = lane & 3;
    const int qt = blockIdx.x, bh = blockIdx.y;
    const int b = bh >> 4, h = bh & 15;
    const size_t rowbase = (size_t)b * SEQ;
    const int q0 = qt * 128;

    const int key = tid >> 1, db = (tid & 1) * 32;   // K/Q staging role
    const int vd = tid >> 2, vq = (tid & 3) * 32;    // V^T staging role

    // ---- stage Q (hi only) into buf0; read fragments ----
    {
        size_t off = (rowbase + q0 + key) * D_MODEL + h * HD + db;
#pragma unroll
        for (int i = 0; i < 4; i++)
            *(uint4*)&sK[key * KSTRS + db + i * 8] = ((const uint4*)(g_qh + off))[i];
    }
    __syncthreads();
    unsigned qfh[4][4];
    {
        int qr = wid * 16;
#pragma unroll
        for (int kk = 0; kk < 4; kk++) {
            int c0 = kk * 16 + 2 * tq;
            qfh[kk][0] = *(const unsigned*)&sK[(qr + g)     * KSTRS + c0];
            qfh[kk][1] = *(const unsigned*)&sK[(qr + g + 8) * KSTRS + c0];
            qfh[kk][2] = *(const unsigned*)&sK[(qr + g)     * KSTRS + c0 + 8];
            qfh[kk][3] = *(const unsigned*)&sK[(qr + g + 8) * KSTRS + c0 + 8];
        }
    }
    __syncthreads();

    const size_t koff0 = (rowbase + key) * D_MODEL + h * HD + db;
    const int    sko   = key * KSTRS + db;
    const size_t ebase = ((size_t)bh * 16 + qt) * (16 * 8 * 8 * 32) + lane;

    // ===== PASS 1: 1-term scores -> E cache + row sums =====
    {
#pragma unroll
        for (int i = 0; i < 4; i++)
            cp16(&sK[sko + i * 8], g_kh + koff0 + i * 8);
        CP_COMMIT();
    }

    float srun0 = 0.f, srun1 = 0.f;

    for (int kt = 0; kt < NKT; kt++) {
        CP_WAIT(0);
        __syncthreads();
        ushort_t* cKh = sK + (kt & 1) * KBUF_SH;
        if (kt + 1 < NKT) {
            ushort_t* nKh = sK + ((kt + 1) & 1) * KBUF_SH;
            size_t off = koff0 + (size_t)(kt + 1) * KT * D_MODEL;
#pragma unroll
            for (int i = 0; i < 4; i++)
                cp16(&nKh[sko + i * 8], g_kh + off + i * 8);
        }
        CP_COMMIT();
        uint4* eptr = g_e + ebase + ((size_t)kt * 8 + wid) * (8 * 32);
#pragma unroll
        for (int jp = 0; jp < 8; jp++) {
            float a2[2][4];
#pragma unroll
            for (int jb = 0; jb < 2; jb++)
#pragma unroll
                for (int r = 0; r < 4; r++) a2[jb][r] = 0.f;
#pragma unroll
            for (int jb = 0; jb < 2; jb++) {
                int n0 = (jp * 2 + jb) * 8 + g;
#pragma unroll
                for (int kk = 0; kk < 4; kk++) {
                    int c0 = kk * 16 + 2 * tq;
                    unsigned b0 = *(const unsigned*)&cKh[n0 * KSTRS + c0];
                    unsigned b1 = *(const unsigned*)&cKh[n0 * KSTRS + c0 + 8];
                    mma16816h(a2[jb], qfh[kk], b0, b1);
                }
            }
            float e00 = __expf(a2[0][0]), e01 = __expf(a2[0][1]);
            float e10 = __expf(a2[0][2]), e11 = __expf(a2[0][3]);
            float e20 = __expf(a2[1][0]), e21 = __expf(a2[1][1]);
            float e30 = __expf(a2[1][2]), e31 = __expf(a2[1][3]);
            uint4 ev;
            ev.x = pack2h(e00, e01);   // row g,   keys jp*16 + 2tq
            ev.y = pack2h(e10, e11);   // row g+8, keys jp*16 + 2tq
            ev.z = pack2h(e20, e21);   // row g,   keys jp*16 + 8 + 2tq
            ev.w = pack2h(e30, e31);   // row g+8, keys jp*16 + 8 + 2tq
            eptr[jp * 32] = ev;
            srun0 += (e00 + e01) + (e20 + e21);
            srun1 += (e10 + e11) + (e30 + e31);
        }
    }
    srun0 += __shfl_xor_sync(0xffffffffu, srun0, 1);
    srun0 += __shfl_xor_sync(0xffffffffu, srun0, 2);
    srun1 += __shfl_xor_sync(0xffffffffu, srun1, 1);
    srun1 += __shfl_xor_sync(0xffffffffu, srun1, 2);
    const float inv0 = 1.0f / srun0, inv1 = 1.0f / srun1;

    // ===== PASS 2: load E, emit A, O = P*V (1-term), V^T double-buffered =====
    float oc[8][4];
#pragma unroll
    for (int j = 0; j < 8; j++)
#pragma unroll
        for (int r = 0; r < 4; r++) oc[j][r] = 0.f;

    const size_t voff0 = ((size_t)bh * HD + vd) * SEQ + vq;
    const int    svo   = vd * VSTRS + vq;

    {   // V[0] into buf0
        CP_WAIT(0);
#pragma unroll
        for (int i = 0; i < 4; i++)
            cp16(&sK[svo + i * 8], g_vth + voff0 + i * 8);
        CP_COMMIT();
    }

    for (int kt = 0; kt < NKT; kt++) {
        CP_WAIT(0);
        __syncthreads();
        ushort_t* cV = sK + (kt & 1) * KBUF_SH;
        if (kt + 1 < NKT) {
            ushort_t* nV = sK + ((kt + 1) & 1) * KBUF_SH;
            size_t off = voff0 + (size_t)(kt + 1) * KT;
#pragma unroll
            for (int i = 0; i < 4; i++)
                cp16(&nV[svo + i * 8], g_vth + off + i * 8);
        }
        CP_COMMIT();

        const uint4* eptr = g_e + ebase + ((size_t)kt * 8 + wid) * (8 * 32);
        uint4 ef[8];
#pragma unroll
        for (int jp = 0; jp < 8; jp++) ef[jp] = eptr[jp * 32];

        unsigned pah[8][4];
#pragma unroll
        for (int jp = 0; jp < 8; jp++) {
            float2 f0 = unpack2h(ef[jp].x);   // row g,   keys +0
            float2 f1 = unpack2h(ef[jp].y);   // row g+8, keys +0
            float2 f2 = unpack2h(ef[jp].z);   // row g,   keys +8
            float2 f3 = unpack2h(ef[jp].w);   // row g+8, keys +8
            f0.x *= inv0; f0.y *= inv0;
            f1.x *= inv1; f1.y *= inv1;
            f2.x *= inv0; f2.y *= inv0;
            f3.x *= inv1; f3.y *= inv1;
            if (writeA) {
                size_t ab = ((size_t)bh * SEQ + q0 + wid * 16) * SEQ
                            + kt * KT + jp * 16;
                *(float2*)(Aout + ab + (size_t)g * SEQ + 2 * tq)           = f0;
                *(float2*)(Aout + ab + (size_t)g * SEQ + 8 + 2 * tq)       = f2;
                *(float2*)(Aout + ab + (size_t)(g + 8) * SEQ + 2 * tq)     = f1;
                *(float2*)(Aout + ab + (size_t)(g + 8) * SEQ + 8 + 2 * tq) = f3;
            }
            pah[jp][0] = pack2h(f0.x, f0.y);
            pah[jp][1] = pack2h(f1.x, f1.y);
            pah[jp][2] = pack2h(f2.x, f2.y);
            pah[jp][3] = pack2h(f3.x, f3.y);
        }

#pragma unroll
        for (int jp = 0; jp < 8; jp++) {
            int kb = jp * 16 + 2 * tq;
#pragma unroll
            for (int n2 = 0; n2 < 8; n2++) {
                int nn = n2 * 8 + g;
                unsigned vb0 = *(const unsigned*)&cV[nn * VSTRS + kb];
                unsigned vb1 = *(const unsigned*)&cV[nn * VSTRS + kb + 8];
                mma16816h(oc[n2], pah[jp], vb0, vb1);
            }
        }
    }

    // ---- epilogue: O -> single fp16 ----
    {
        size_t r0 = rowbase + q0 + wid * 16 + g;
#pragma unroll
        for (int n2 = 0; n2 < 8; n2++) {
            int col = h * HD + n2 * 8 + 2 * tq;
            *(unsigned*)(g_oh + r0 * D_MODEL + col)       = pack2h(oc[n2][0], oc[n2][1]);
            *(unsigned*)(g_oh + (r0 + 8) * D_MODEL + col) = pack2h(oc[n2][2], oc[n2][3]);
        }
    }
}

// ---------------------------------------------------------------------------
extern "C" void kernel_launch(void* const* d_in, const int* in_sizes, int n_in,
                              void* d_out, int out_size)
{
    (void)in_sizes; (void)n_in;
    const float* x  = (const float*)d_in[0];
    // d_in[1] = key_indices (unused by the reference)
    const float* Wq = (const float*)d_in[2];
    const float* Wk = (const float*)d_in[3];
    const float* Wv = (const float*)d_in[4];
    const float* Wo = (const float*)d_in[5];
    const float* bo = (const float*)d_in[6];
    float* out = (float*)d_out;

    ushort_t *xh, *wq, *wk, *wv, *wo;
    cudaGetSymbolAddress((void**)&xh, g_xh);
    cudaGetSymbolAddress((void**)&wq, g_wq);  cudaGetSymbolAddress((void**)&wk, g_wk);
    cudaGetSymbolAddress((void**)&wv, g_wv);  cudaGetSymbolAddress((void**)&wo, g_wo);

    // convert inputs to fp16
    const int nx2 = (M_ROWS * D_MODEL) / 2;
    const int nw2 = (D_MODEL * D_MODEL) / 2;
    cvt_h<<<nx2 / 256, 256>>>(x, (unsigned*)xh, nx2);
    cvt_w4<<<dim3(nw2 / 256, 4), 256>>>(Wq, Wk, Wv, Wo,
                                        (unsigned*)wq, (unsigned*)wk,
                                        (unsigned*)wv, (unsigned*)wo, nw2);

    cudaFuncSetAttribute(gemm_qkv, cudaFuncAttributeMaxDynamicSharedMemorySize,
                         GEMM_SMEM);
    cudaFuncSetAttribute(gemm_out, cudaFuncAttributeMaxDynamicSharedMemorySize,
                         GEMM_SMEM);

    // fused Q/K/V projections (Q carries softmax scale 0.125)
    gemm_qkv<<<dim3(24, M_ROWS / 128), 256, GEMM_SMEM>>>();

    vtrans_kernel<<<dim3(SEQ / 32, HD / 32, B_SZ * N_HEAD), dim3(32, 8)>>>();

    const size_t OUT_ELEMS = (size_t)M_ROWS * D_MODEL;
    const size_t A_ELEMS   = (size_t)B_SZ * N_HEAD * SEQ * SEQ;
    int writeA = ((size_t)out_size >= OUT_ELEMS + A_ELEMS) ? 1 : 0;
    float* Aout = out + OUT_ELEMS;

    cudaFuncSetAttribute(attn2, cudaFuncAttributeMaxDynamicSharedMemorySize,
                         ATT_SMEM);
    attn2<<<dim3(SEQ / 128, B_SZ * N_HEAD), dim3(256), ATT_SMEM>>>(Aout, writeA);

    gemm_out<<<dim3(D_MODEL / 128, M_ROWS / 128), 256, GEMM_SMEM>>>(out, bo);
}